// round 3
// baseline (speedup 1.0000x reference)
#include <cuda_runtime.h>
#include <cuda_bf16.h>
#include <math.h>

// ---------------------------------------------------------------------------
// BailingMoeV2Gate: logits = X @ W^T ; scores = sigmoid(logits);
// group-limited top-k routing (8 groups of 32, top-4 groups by top2-sum,
// top-8 experts, weights = gathered/(sum)*2.5).
// Output (float32 concat): [T*8] topk_idx, [T*8] topk_weight, [T*256] logits.
// ---------------------------------------------------------------------------

// Scratch for logits in case out_size doesn't include the logits region.
__device__ float g_logits_scratch[16384 * 256];

// ======================== fp32 GEMM: C[T,E] = A[T,H] * B[E,H]^T =============
// Tile: BM=128, BN=64, BK=16. 256 threads, each computes 8x4.
__global__ __launch_bounds__(256) void gemm_f32(
    const float* __restrict__ A, const float* __restrict__ B,
    float* __restrict__ C, int T, int E, int H)
{
    __shared__ float As[16][132];  // [k][m], padded
    __shared__ float Bs[16][68];   // [k][n], padded

    const int tid = threadIdx.x;
    const int bm = blockIdx.y * 128;
    const int bn = blockIdx.x * 64;

    // loader mapping: 256 threads, float4 each
    const int ar = tid >> 2;          // 0..63
    const int ac = (tid & 3) << 2;    // 0,4,8,12

    // compute mapping
    const int tx = tid & 15;          // N
    const int ty = tid >> 4;          // M

    const float* Ap0 = A + (size_t)(bm + ar) * H + ac;
    const float* Ap1 = A + (size_t)(bm + ar + 64) * H + ac;
    const float* Bp  = B + (size_t)(bn + ar) * H + ac;

    float acc[8][4];
#pragma unroll
    for (int i = 0; i < 8; i++)
#pragma unroll
        for (int j = 0; j < 4; j++) acc[i][j] = 0.0f;

    float4 ra0 = *(const float4*)(Ap0);
    float4 ra1 = *(const float4*)(Ap1);
    float4 rb  = *(const float4*)(Bp);

    for (int k0 = 16;; k0 += 16) {
        // stage registers -> shared (transposed)
        As[ac + 0][ar] = ra0.x; As[ac + 1][ar] = ra0.y;
        As[ac + 2][ar] = ra0.z; As[ac + 3][ar] = ra0.w;
        As[ac + 0][ar + 64] = ra1.x; As[ac + 1][ar + 64] = ra1.y;
        As[ac + 2][ar + 64] = ra1.z; As[ac + 3][ar + 64] = ra1.w;
        Bs[ac + 0][ar] = rb.x; Bs[ac + 1][ar] = rb.y;
        Bs[ac + 2][ar] = rb.z; Bs[ac + 3][ar] = rb.w;
        __syncthreads();

        const bool more = (k0 < H);
        if (more) {  // prefetch next K-block into registers
            ra0 = *(const float4*)(Ap0 + k0);
            ra1 = *(const float4*)(Ap1 + k0);
            rb  = *(const float4*)(Bp + k0);
        }

#pragma unroll
        for (int k = 0; k < 16; k++) {
            float a[8], b[4];
            *(float4*)&a[0] = *(const float4*)&As[k][ty * 8];
            *(float4*)&a[4] = *(const float4*)&As[k][ty * 8 + 4];
            *(float4*)&b[0] = *(const float4*)&Bs[k][tx * 4];
#pragma unroll
            for (int i = 0; i < 8; i++)
#pragma unroll
                for (int j = 0; j < 4; j++)
                    acc[i][j] = fmaf(a[i], b[j], acc[i][j]);
        }
        if (!more) break;
        __syncthreads();
    }

#pragma unroll
    for (int i = 0; i < 8; i++) {
        float4 v = make_float4(acc[i][0], acc[i][1], acc[i][2], acc[i][3]);
        *(float4*)(C + (size_t)(bm + ty * 8 + i) * E + bn + tx * 4) = v;
    }
}

// ======================== routing: one warp per token =======================
// E=256, 8 groups of 32, topk_group=4, top_k=8. Replicates jax.lax.top_k
// tie-breaking: values descending, lower index first on ties.
__global__ __launch_bounds__(256) void routing_kernel(
    const float* __restrict__ logits, const float* __restrict__ bias,
    float* __restrict__ out_idx, float* __restrict__ out_w, int T)
{
    const int wip  = threadIdx.x >> 5;
    const int lane = threadIdx.x & 31;
    const int t = blockIdx.x * 8 + wip;
    if (t >= T) return;

    __shared__ float s_sc[8][256];   // sigmoid scores
    __shared__ float s_sr[8][256];   // scores + bias (routing scores)
    __shared__ float s_gv[8][8];     // winners: gathered sigmoid score
    __shared__ int   s_gi[8][8];     // winners: expert index

    float* sc = s_sc[wip];
    float* sr = s_sr[wip];
    const float* lrow = logits + (size_t)t * 256;

#pragma unroll
    for (int i = 0; i < 8; i++) {
        int e = i * 32 + lane;
        float l = lrow[e];
        float s = 1.0f / (1.0f + expf(-l));
        sc[e] = s;
        sr[e] = s + bias[e];
    }
    __syncwarp();

    // group scores (top1 + top2 within each 32-expert group), lanes 0..7
    float gscore = -INFINITY;
    if (lane < 8) {
        float m1 = -INFINITY, m2 = -INFINITY;
#pragma unroll
        for (int j = 0; j < 32; j++) {
            float v = sr[lane * 32 + ((j + lane * 4) & 31)];  // stagger banks
            if (v > m1) { m2 = m1; m1 = v; }
            else if (v > m2) { m2 = v; }
        }
        gscore = m1 + m2;
    }

    // broadcast group scores; every lane redundantly selects top-4 groups
    float gs[8];
#pragma unroll
    for (int g = 0; g < 8; g++) gs[g] = __shfl_sync(0xffffffffu, gscore, g);
    unsigned gmask = 0;
#pragma unroll
    for (int k = 0; k < 4; k++) {
        int bi = -1; float bv = -INFINITY;
#pragma unroll
        for (int g = 0; g < 8; g++) {
            bool taken = (gmask >> g) & 1u;
            if (!taken && gs[g] > bv) { bv = gs[g]; bi = g; }  // strict > : lower idx wins ties
        }
        gmask |= 1u << bi;
    }

    // per-lane masked routing scores: expert e = i*32 + lane -> group i
    float vals[8];
#pragma unroll
    for (int i = 0; i < 8; i++)
        vals[i] = ((gmask >> i) & 1u) ? sr[i * 32 + lane] : -INFINITY;

    // iterative top-8 with warp argmax (value desc, index asc)
    float sum = 0.0f;
    for (int k = 0; k < 8; k++) {
        float bv = -INFINITY; int bi = 0x7fffffff;
#pragma unroll
        for (int i = 0; i < 8; i++) {
            int e = i * 32 + lane;
            if (vals[i] > bv || (vals[i] == bv && e < bi)) { bv = vals[i]; bi = e; }
        }
#pragma unroll
        for (int off = 16; off; off >>= 1) {
            float ov = __shfl_xor_sync(0xffffffffu, bv, off);
            int   oi = __shfl_xor_sync(0xffffffffu, bi, off);
            if (ov > bv || (ov == bv && oi < bi)) { bv = ov; bi = oi; }
        }
        // all lanes agree on winner bi; owner retires it
        if ((bi & 31) == lane) vals[bi >> 5] = -INFINITY;
        float g = sc[bi];  // gather the SIGMOID score (no bias)
        sum += g;
        if (lane == 0) { s_gv[wip][k] = g; s_gi[wip][k] = bi; }
    }
    __syncwarp();

    if (lane < 8) {
        float w = s_gv[wip][lane] / (sum + 1e-20f) * 2.5f;
        out_w[(size_t)t * 8 + lane]   = w;
        out_idx[(size_t)t * 8 + lane] = (float)s_gi[wip][lane];
    }
}

// ============================== launch ======================================
extern "C" void kernel_launch(void* const* d_in, const int* in_sizes, int n_in,
                              void* d_out, int out_size)
{
    const float* X    = (const float*)d_in[0];  // [T, H]
    const float* W    = (const float*)d_in[1];  // [E, H]
    const float* bias = (const float*)d_in[2];  // [E]

    const int E = in_sizes[2];
    const int H = in_sizes[1] / E;
    const int T = in_sizes[0] / H;

    float* out     = (float*)d_out;
    float* out_idx = out;
    float* out_w   = out + (size_t)T * 8;

    float* logits;
    if ((size_t)out_size >= (size_t)T * 16 + (size_t)T * E) {
        logits = out + (size_t)T * 16;
    } else {
        float* p;
        cudaGetSymbolAddress((void**)&p, g_logits_scratch);
        logits = p;
    }

    dim3 grid(E / 64, T / 128);
    gemm_f32<<<grid, 256>>>(X, W, logits, T, E, H);
    routing_kernel<<<(T + 7) / 8, 256>>>(logits, bias, out_idx, out_w, T);
}

// round 7
// speedup vs baseline: 1.1736x; 1.1736x over previous
#include <cuda_runtime.h>
#include <cuda_bf16.h>
#include <math.h>
#include <stdint.h>

// ---------------------------------------------------------------------------
// BailingMoeV2Gate (plain sm_103 target, no tcgen05):
// logits = X[T,4096] @ W[256,4096]^T via mma.sync.m16n8k16 bf16 3-way split,
// 6 products {00,01,10,11,20,02}. Short 6-mma chains seeded with C=0, master
// accumulation in software fp32 (RN) -> avoids tensor-core RZ-chain bias.
// Then sigmoid + group-limited top-k routing.
// Output (fp32 concat): [T*8] idx, [T*8] weights, [T*256] logits.
// ---------------------------------------------------------------------------

#define HID   4096
#define NEXP  256
#define KC    32
#define NST   (HID / KC)   // 128 stages

__device__ float g_logits_scratch[16384 * 256];
__device__ __nv_bfloat16 g_W0[NEXP * HID];
__device__ __nv_bfloat16 g_W1[NEXP * HID];
__device__ __nv_bfloat16 g_W2[NEXP * HID];

__device__ __forceinline__ uint32_t smem_u32(const void* p) {
    uint32_t a;
    asm("{ .reg .u64 t; cvta.to.shared.u64 t, %1; cvt.u32.u64 %0, t; }"
        : "=r"(a) : "l"(p));
    return a;
}

// fresh chain: D = A*B + 0   (D regs distinct from C; C = zero inputs)
#define MMA_INIT(d, a, b)                                                  \
    asm volatile(                                                          \
        "mma.sync.aligned.m16n8k16.row.col.f32.bf16.bf16.f32 "             \
        "{%0,%1,%2,%3}, {%4,%5,%6,%7}, {%8,%9}, {%10,%11,%12,%13};"        \
        : "=f"((d)[0]), "=f"((d)[1]), "=f"((d)[2]), "=f"((d)[3])           \
        : "r"((a)[0]), "r"((a)[1]), "r"((a)[2]), "r"((a)[3]),              \
          "r"((b)[0]), "r"((b)[1]),                                        \
          "f"(0.0f), "f"(0.0f), "f"(0.0f), "f"(0.0f))

#define MMA_ACC(d, a, b)                                                   \
    asm volatile(                                                          \
        "mma.sync.aligned.m16n8k16.row.col.f32.bf16.bf16.f32 "             \
        "{%0,%1,%2,%3}, {%4,%5,%6,%7}, {%8,%9}, {%0,%1,%2,%3};"            \
        : "+f"((d)[0]), "+f"((d)[1]), "+f"((d)[2]), "+f"((d)[3])           \
        : "r"((a)[0]), "r"((a)[1]), "r"((a)[2]), "r"((a)[3]),              \
          "r"((b)[0]), "r"((b)[1]))

#define LDMATRIX_X4(r, addr)                                               \
    asm volatile("ldmatrix.sync.aligned.m8n8.x4.shared.b16 "               \
                 "{%0,%1,%2,%3}, [%4];"                                    \
                 : "=r"((r)[0]), "=r"((r)[1]), "=r"((r)[2]), "=r"((r)[3])  \
                 : "r"(addr))

#define LDMATRIX_X2(r, addr)                                               \
    asm volatile("ldmatrix.sync.aligned.m8n8.x2.shared.b16 {%0,%1}, [%2];" \
                 : "=r"((r)[0]), "=r"((r)[1]) : "r"(addr))

#define CP_ASYNC16(dst, src)                                               \
    asm volatile("{ .reg .u64 g; cvta.to.global.u64 g, %1; "               \
                 "cp.async.ca.shared.global [%0], [g], 16; }"              \
                 :: "r"(dst), "l"(src))

// ====================== W split pre-kernel =================================
__global__ __launch_bounds__(256) void wsplit_kernel(const float* __restrict__ W) {
    size_t i = ((size_t)blockIdx.x * 256 + threadIdx.x) * 4;
    float4 v = *(const float4*)(W + i);
    float a[4] = {v.x, v.y, v.z, v.w};
#pragma unroll
    for (int j = 0; j < 4; j++) {
        float x = a[j];
        __nv_bfloat16 w0 = __float2bfloat16_rn(x);
        float r1 = x - __bfloat162float(w0);
        __nv_bfloat16 w1 = __float2bfloat16_rn(r1);
        float r2 = r1 - __bfloat162float(w1);
        __nv_bfloat16 w2 = __float2bfloat16_rn(r2);
        g_W0[i + j] = w0;
        g_W1[i + j] = w1;
        g_W2[i + j] = w2;
    }
}

// ====================== split-bf16 mma.sync GEMM ===========================
// Grid (2, T/128): CTA tile M=128, N=128. 256 threads = 8 warps (4M x 2N),
// warp tile 32x64. KC=32 per stage (2 k16 steps), 2-stage double buffer.
// SMEM bf16 tiles, 80B padded row stride (32 bf16 data + 16B pad).
#define A_ROW    80
#define A_SPLIT  (128 * A_ROW)       // 10240
#define A_BUF    (3 * A_SPLIT)       // 30720
#define B_OFF    (2 * A_BUF)         // 61440
#define B_SPLIT  (128 * A_ROW)
#define B_BUF    (3 * B_SPLIT)
#define GEMM_SMEM (B_OFF + 2 * B_BUF)  // 122880

__global__ void __launch_bounds__(256, 1) gemm_bf16_split(
    const float* __restrict__ X, float* __restrict__ C)
{
    extern __shared__ char smem[];
    const uint32_t sb = smem_u32(smem);
    const int tid  = threadIdx.x;
    const int lane = tid & 31;
    const int wid  = tid >> 5;
    const int wm   = wid >> 1;      // 0..3 (M)
    const int wn   = wid & 1;       // 0..1 (N)
    const int bm   = blockIdx.y * 128;
    const int bn   = blockIdx.x * 128;

    // ---- A loader: 256 threads, 16 floats each: row = tid>>1, koff=(tid&1)*16
    const int ar  = tid >> 1;
    const int akh = tid & 1;
    const float* aptr = X + (size_t)(bm + ar) * HID + akh * 16;

    // ---- B loader: 6 cp.async 16B chunks per thread per stage.
    // chunk j = tid*6 + c : p = j/512, row = (j%512)>>2, ch = j&3
    const __nv_bfloat16* wbase[3] = {g_W0, g_W1, g_W2};

    float acc[2][8][4];
#pragma unroll
    for (int m = 0; m < 2; m++)
#pragma unroll
        for (int n = 0; n < 8; n++)
#pragma unroll
            for (int k = 0; k < 4; k++) acc[m][n][k] = 0.0f;

    float4 xs0, xs1, xs2, xs3;   // 16 staged fp32

    auto a_ldg = [&](int s) {
        const float* p = aptr + s * KC;
        xs0 = *(const float4*)(p);
        xs1 = *(const float4*)(p + 4);
        xs2 = *(const float4*)(p + 8);
        xs3 = *(const float4*)(p + 12);
    };
    auto b_cpasync = [&](int s, int b) {
#pragma unroll
        for (int c = 0; c < 6; c++) {
            int j   = tid * 6 + c;
            int p   = j >> 9;            // /512
            int rem = j & 511;
            int row = rem >> 2;
            int ch  = rem & 3;
            const char* src = (const char*)(wbase[p] + (size_t)(bn + row) * HID + s * KC) + ch * 16;
            uint32_t dst = sb + B_OFF + b * B_BUF + p * B_SPLIT + row * A_ROW + ch * 16;
            CP_ASYNC16(dst, src);
        }
        asm volatile("cp.async.commit_group;" ::: "memory");
    };
    auto a_sts = [&](int b) {
        float xv[16] = {xs0.x, xs0.y, xs0.z, xs0.w, xs1.x, xs1.y, xs1.z, xs1.w,
                        xs2.x, xs2.y, xs2.z, xs2.w, xs3.x, xs3.y, xs3.z, xs3.w};
        __nv_bfloat162 h0[8], h1[8], h2[8];
#pragma unroll
        for (int i = 0; i < 8; i++) {
            float xa = xv[2 * i], xb = xv[2 * i + 1];
            __nv_bfloat16 a0 = __float2bfloat16_rn(xa);
            float ra = xa - __bfloat162float(a0);
            __nv_bfloat16 a1 = __float2bfloat16_rn(ra);
            float ra2 = ra - __bfloat162float(a1);
            __nv_bfloat16 a2 = __float2bfloat16_rn(ra2);
            __nv_bfloat16 b0 = __float2bfloat16_rn(xb);
            float rb = xb - __bfloat162float(b0);
            __nv_bfloat16 b1 = __float2bfloat16_rn(rb);
            float rb2 = rb - __bfloat162float(b1);
            __nv_bfloat16 b2 = __float2bfloat16_rn(rb2);
            h0[i] = __nv_bfloat162(a0, b0);
            h1[i] = __nv_bfloat162(a1, b1);
            h2[i] = __nv_bfloat162(a2, b2);
        }
        char* base = smem + b * A_BUF + ar * A_ROW + akh * 32;
        *(uint4*)(base)                    = ((const uint4*)h0)[0];
        *(uint4*)(base + 16)               = ((const uint4*)h0)[1];
        *(uint4*)(base + A_SPLIT)          = ((const uint4*)h1)[0];
        *(uint4*)(base + A_SPLIT + 16)     = ((const uint4*)h1)[1];
        *(uint4*)(base + 2 * A_SPLIT)      = ((const uint4*)h2)[0];
        *(uint4*)(base + 2 * A_SPLIT + 16) = ((const uint4*)h2)[1];
    };

    // ---- ldmatrix addresses ----
    // A x4: matrix mt=lane>>3: rows (lane&7)+8*(mt&1), k-half = mt>>1 (16B)
    const int a_mt = lane >> 3;
    const uint32_t a_addr0 = sb + (wm * 32 + (lane & 7) + ((a_mt & 1) << 3)) * A_ROW
                           + (a_mt >> 1) * 16;
    // B x2: lanes 0-15: rows n = (l15&7), k-half = (l15>>3)*16
    const int l15 = lane & 15;
    const uint32_t b_addr0 = sb + B_OFF + (wn * 64 + (l15 & 7)) * A_ROW
                           + (l15 >> 3) * 16;

    auto compute = [&](int b) {
#pragma unroll
        for (int kk = 0; kk < 2; kk++) {
            uint32_t af[3][2][4];
#pragma unroll
            for (int p = 0; p < 3; p++)
#pragma unroll
                for (int m = 0; m < 2; m++)
                    LDMATRIX_X4(af[p][m],
                        a_addr0 + b * A_BUF + p * A_SPLIT + m * 16 * A_ROW + kk * 32);
#pragma unroll
            for (int nt = 0; nt < 8; nt++) {
                uint32_t bf[3][2];
#pragma unroll
                for (int p = 0; p < 3; p++)
                    LDMATRIX_X2(bf[p],
                        b_addr0 + b * B_BUF + p * B_SPLIT + nt * 8 * A_ROW + kk * 32);
#pragma unroll
                for (int m = 0; m < 2; m++) {
                    float ch[4];
                    MMA_INIT(ch, af[0][m], bf[0]);   // x0*w0 (fresh, C=0)
                    MMA_ACC (ch, af[0][m], bf[1]);   // x0*w1
                    MMA_ACC (ch, af[1][m], bf[0]);   // x1*w0
                    MMA_ACC (ch, af[1][m], bf[1]);   // x1*w1
                    MMA_ACC (ch, af[0][m], bf[2]);   // x0*w2
                    MMA_ACC (ch, af[2][m], bf[0]);   // x2*w0
                    acc[m][nt][0] += ch[0];          // master accum, RN fp32
                    acc[m][nt][1] += ch[1];
                    acc[m][nt][2] += ch[2];
                    acc[m][nt][3] += ch[3];
                }
            }
        }
    };

    // ---- prologue ----
    a_ldg(0);
    b_cpasync(0, 0);
    a_sts(0);
    asm volatile("cp.async.wait_group 0;" ::: "memory");
    __syncthreads();

    // ---- mainloop ----
    for (int s = 0; s < NST; s++) {
        const int b = s & 1;
        const bool more = (s + 1 < NST);
        if (more) {
            a_ldg(s + 1);
            b_cpasync(s + 1, b ^ 1);
        }
        compute(b);
        if (more) a_sts(b ^ 1);
        asm volatile("cp.async.wait_group 0;" ::: "memory");
        __syncthreads();
    }

    // ---- epilogue ----
#pragma unroll
    for (int m = 0; m < 2; m++) {
#pragma unroll
        for (int nt = 0; nt < 8; nt++) {
            const int row = bm + wm * 32 + m * 16 + (lane >> 2);
            const int col = bn + wn * 64 + nt * 8 + ((lane & 3) << 1);
            float* cp = C + (size_t)row * NEXP + col;
            *(float2*)cp = make_float2(acc[m][nt][0], acc[m][nt][1]);
            *(float2*)(cp + 8 * NEXP) = make_float2(acc[m][nt][2], acc[m][nt][3]);
        }
    }
}

// ======================== routing: one warp per token =======================
__global__ __launch_bounds__(256) void routing_kernel(
    const float* __restrict__ logits, const float* __restrict__ bias,
    float* __restrict__ out_idx, float* __restrict__ out_w, int T)
{
    const int wip  = threadIdx.x >> 5;
    const int lane = threadIdx.x & 31;
    const int t = blockIdx.x * 8 + wip;
    if (t >= T) return;

    __shared__ float s_sc[8][256];
    __shared__ float s_sr[8][256];
    __shared__ float s_gv[8][8];
    __shared__ int   s_gi[8][8];

    float* sc = s_sc[wip];
    float* sr = s_sr[wip];
    const float* lrow = logits + (size_t)t * 256;

#pragma unroll
    for (int i = 0; i < 8; i++) {
        int e = i * 32 + lane;
        float l = lrow[e];
        float s = 1.0f / (1.0f + expf(-l));
        sc[e] = s;
        sr[e] = s + bias[e];
    }
    __syncwarp();

    float gscore = -INFINITY;
    if (lane < 8) {
        float m1 = -INFINITY, m2 = -INFINITY;
#pragma unroll
        for (int j = 0; j < 32; j++) {
            float v = sr[lane * 32 + ((j + lane * 4) & 31)];
            if (v > m1) { m2 = m1; m1 = v; }
            else if (v > m2) { m2 = v; }
        }
        gscore = m1 + m2;
    }

    float gs[8];
#pragma unroll
    for (int g = 0; g < 8; g++) gs[g] = __shfl_sync(0xffffffffu, gscore, g);
    unsigned gmask = 0;
#pragma unroll
    for (int k = 0; k < 4; k++) {
        int bi = -1; float bv = -INFINITY;
#pragma unroll
        for (int g = 0; g < 8; g++) {
            bool taken = (gmask >> g) & 1u;
            if (!taken && gs[g] > bv) { bv = gs[g]; bi = g; }
        }
        gmask |= 1u << bi;
    }

    float vals[8];
#pragma unroll
    for (int i = 0; i < 8; i++)
        vals[i] = ((gmask >> i) & 1u) ? sr[i * 32 + lane] : -INFINITY;

    float sum = 0.0f;
    for (int k = 0; k < 8; k++) {
        float bv = -INFINITY; int bi = 0x7fffffff;
#pragma unroll
        for (int i = 0; i < 8; i++) {
            int e = i * 32 + lane;
            if (vals[i] > bv || (vals[i] == bv && e < bi)) { bv = vals[i]; bi = e; }
        }
#pragma unroll
        for (int off = 16; off; off >>= 1) {
            float ov = __shfl_xor_sync(0xffffffffu, bv, off);
            int   oi = __shfl_xor_sync(0xffffffffu, bi, off);
            if (ov > bv || (ov == bv && oi < bi)) { bv = ov; bi = oi; }
        }
        if ((bi & 31) == lane) vals[bi >> 5] = -INFINITY;
        float g = sc[bi];
        sum += g;
        if (lane == 0) { s_gv[wip][k] = g; s_gi[wip][k] = bi; }
    }
    __syncwarp();

    if (lane < 8) {
        float w = s_gv[wip][lane] / (sum + 1e-20f) * 2.5f;
        out_w[(size_t)t * 8 + lane]   = w;
        out_idx[(size_t)t * 8 + lane] = (float)s_gi[wip][lane];
    }
}

// ============================== launch ======================================
extern "C" void kernel_launch(void* const* d_in, const int* in_sizes, int n_in,
                              void* d_out, int out_size)
{
    const float* X    = (const float*)d_in[0];  // [T, H]
    const float* W    = (const float*)d_in[1];  // [E, H]
    const float* bias = (const float*)d_in[2];  // [E]

    const int E = in_sizes[2];
    const int H = in_sizes[1] / E;
    const int T = in_sizes[0] / H;

    float* out     = (float*)d_out;
    float* out_idx = out;
    float* out_w   = out + (size_t)T * 8;

    float* logits;
    if ((size_t)out_size >= (size_t)T * 16 + (size_t)T * E) {
        logits = out + (size_t)T * 16;
    } else {
        float* p;
        cudaGetSymbolAddress((void**)&p, g_logits_scratch);
        logits = p;
    }

    // 1) W -> three bf16 split arrays
    wsplit_kernel<<<(E * H / 4 + 255) / 256, 256>>>(W);

    // 2) tensor-core split GEMM -> logits
    cudaFuncSetAttribute(gemm_bf16_split,
                         cudaFuncAttributeMaxDynamicSharedMemorySize, GEMM_SMEM);
    dim3 grid(E / 128, T / 128);
    gemm_bf16_split<<<grid, 256, GEMM_SMEM>>>(X, logits);

    // 3) routing
    routing_kernel<<<(T + 7) / 8, 256>>>(logits, bias, out_idx, out_w, T);
}

// round 9
// speedup vs baseline: 1.5976x; 1.3613x over previous
#include <cuda_runtime.h>
#include <cuda_fp16.h>
#include <math.h>
#include <stdint.h>

// ---------------------------------------------------------------------------
// BailingMoeV2Gate (plain sm_103 target, no tcgen05):
// logits = X[T,4096] @ W[256,4096]^T via mma.sync.m16n8k16 fp16 2-way split,
// 3 products {x0w0, x0w1, x1w0}. W pre-scaled by 2^12, X by 2^4 (keeps split
// residuals in normal fp16 range); epilogue x 2^-16. One 6-mma RZ chain per
// stage (C=0 seeded) + Kahan RN master accumulation -> ~1.5e-7 logits.
// Then sigmoid + group-limited top-k routing.
// Output (fp32 concat): [T*8] idx, [T*8] weights, [T*256] logits.
// ---------------------------------------------------------------------------

#define HID   4096
#define NEXP  256
#define KC    32
#define NST   (HID / KC)   // 128 stages

__device__ float g_logits_scratch[16384 * 256];
__device__ __half g_W0[NEXP * HID];   // fp16(W * 4096)
__device__ __half g_W1[NEXP * HID];   // fp16 residual

__device__ __forceinline__ uint32_t smem_u32(const void* p) {
    uint32_t a;
    asm("{ .reg .u64 t; cvta.to.shared.u64 t, %1; cvt.u32.u64 %0, t; }"
        : "=r"(a) : "l"(p));
    return a;
}

#define MMA_INIT(d, a, b)                                                  \
    asm volatile(                                                          \
        "mma.sync.aligned.m16n8k16.row.col.f32.f16.f16.f32 "               \
        "{%0,%1,%2,%3}, {%4,%5,%6,%7}, {%8,%9}, {%10,%11,%12,%13};"        \
        : "=f"((d)[0]), "=f"((d)[1]), "=f"((d)[2]), "=f"((d)[3])           \
        : "r"((a)[0]), "r"((a)[1]), "r"((a)[2]), "r"((a)[3]),              \
          "r"((b)[0]), "r"((b)[1]),                                        \
          "f"(0.0f), "f"(0.0f), "f"(0.0f), "f"(0.0f))

#define MMA_ACC(d, a, b)                                                   \
    asm volatile(                                                          \
        "mma.sync.aligned.m16n8k16.row.col.f32.f16.f16.f32 "               \
        "{%0,%1,%2,%3}, {%4,%5,%6,%7}, {%8,%9}, {%0,%1,%2,%3};"            \
        : "+f"((d)[0]), "+f"((d)[1]), "+f"((d)[2]), "+f"((d)[3])           \
        : "r"((a)[0]), "r"((a)[1]), "r"((a)[2]), "r"((a)[3]),              \
          "r"((b)[0]), "r"((b)[1]))

#define LDMATRIX_X4(r, addr)                                               \
    asm volatile("ldmatrix.sync.aligned.m8n8.x4.shared.b16 "               \
                 "{%0,%1,%2,%3}, [%4];"                                    \
                 : "=r"((r)[0]), "=r"((r)[1]), "=r"((r)[2]), "=r"((r)[3])  \
                 : "r"(addr))

#define LDMATRIX_X2(r, addr)                                               \
    asm volatile("ldmatrix.sync.aligned.m8n8.x2.shared.b16 {%0,%1}, [%2];" \
                 : "=r"((r)[0]), "=r"((r)[1]) : "r"(addr))

#define CP_ASYNC16(dst, src)                                               \
    asm volatile("{ .reg .u64 g; cvta.to.global.u64 g, %1; "               \
                 "cp.async.ca.shared.global [%0], [g], 16; }"              \
                 :: "r"(dst), "l"(src))

// ====================== W split pre-kernel =================================
// w' = w * 4096 (exact). w0 = fp16(w'), w1 = fp16(w' - w0).
__global__ __launch_bounds__(256) void wsplit_kernel(const float* __restrict__ W) {
    size_t i = ((size_t)blockIdx.x * 256 + threadIdx.x) * 4;
    float4 v = *(const float4*)(W + i);
    float a[4] = {v.x, v.y, v.z, v.w};
#pragma unroll
    for (int j = 0; j < 4; j++) {
        float x = a[j] * 4096.0f;
        __half w0 = __float2half_rn(x);
        float r1 = x - __half2float(w0);
        __half w1 = __float2half_rn(r1);
        g_W0[i + j] = w0;
        g_W1[i + j] = w1;
    }
}

// ====================== split-fp16 mma.sync GEMM ===========================
// Grid (2, T/128): CTA tile M=128, N=128. 256 threads = 8 warps (4M x 2N),
// warp tile 32x64. KC=32 per stage (2 k16 steps), 2-stage double buffer.
// SMEM fp16 tiles, 80B padded row stride (64B data + 16B pad).
#define A_ROW    80
#define A_SPLIT  (128 * A_ROW)       // 10240
#define A_BUF    (2 * A_SPLIT)       // 20480
#define B_OFF    (2 * A_BUF)         // 40960
#define B_SPLIT  (128 * A_ROW)
#define B_BUF    (2 * B_SPLIT)
#define GEMM_SMEM (B_OFF + 2 * B_BUF)  // 81920

__global__ void __launch_bounds__(256, 1) gemm_fp16_split(
    const float* __restrict__ X, float* __restrict__ C)
{
    extern __shared__ char smem[];
    const uint32_t sb = smem_u32(smem);
    const int tid  = threadIdx.x;
    const int lane = tid & 31;
    const int wid  = tid >> 5;
    const int wm   = wid >> 1;      // 0..3 (M)
    const int wn   = wid & 1;       // 0..1 (N)
    const int bm   = blockIdx.y * 128;
    const int bn   = blockIdx.x * 128;

    // ---- A loader: 256 threads, 16 floats each ----
    const int ar  = tid >> 1;
    const int akh = tid & 1;
    const float* aptr = X + (size_t)(bm + ar) * HID + akh * 16;

    // ---- B loader: 4 cp.async 16B chunks per thread per stage ----
    // j = tid*4+c in [0,1024): p = j>>9, row = (j&511)>>2, ch = j&3
    const __half* wbase[2] = {g_W0, g_W1};

    float acc[2][8][4], cmp[2][8][4];
#pragma unroll
    for (int m = 0; m < 2; m++)
#pragma unroll
        for (int n = 0; n < 8; n++)
#pragma unroll
            for (int k = 0; k < 4; k++) { acc[m][n][k] = 0.0f; cmp[m][n][k] = 0.0f; }

    float4 xs0, xs1, xs2, xs3;   // 16 staged fp32

    auto a_ldg = [&](int s) {
        const float* p = aptr + s * KC;
        xs0 = *(const float4*)(p);
        xs1 = *(const float4*)(p + 4);
        xs2 = *(const float4*)(p + 8);
        xs3 = *(const float4*)(p + 12);
    };
    auto b_cpasync = [&](int s, int b) {
#pragma unroll
        for (int c = 0; c < 4; c++) {
            int j   = tid * 4 + c;
            int p   = j >> 9;
            int rem = j & 511;
            int row = rem >> 2;
            int ch  = rem & 3;
            const char* src = (const char*)(wbase[p] + (size_t)(bn + row) * HID + s * KC) + ch * 16;
            uint32_t dst = sb + B_OFF + b * B_BUF + p * B_SPLIT + row * A_ROW + ch * 16;
            CP_ASYNC16(dst, src);
        }
        asm volatile("cp.async.commit_group;" ::: "memory");
    };
    auto a_sts = [&](int b) {
        float xv[16] = {xs0.x, xs0.y, xs0.z, xs0.w, xs1.x, xs1.y, xs1.z, xs1.w,
                        xs2.x, xs2.y, xs2.z, xs2.w, xs3.x, xs3.y, xs3.z, xs3.w};
        __half2 h0[8], h1[8];
#pragma unroll
        for (int i = 0; i < 8; i++) {
            float xa = xv[2 * i] * 16.0f;       // exact scale
            float xb = xv[2 * i + 1] * 16.0f;
            __half a0 = __float2half_rn(xa);
            float ra = xa - __half2float(a0);
            __half a1 = __float2half_rn(ra);
            __half b0 = __float2half_rn(xb);
            float rb = xb - __half2float(b0);
            __half b1 = __float2half_rn(rb);
            h0[i] = __half2(a0, b0);
            h1[i] = __half2(a1, b1);
        }
        char* base = smem + b * A_BUF + ar * A_ROW + akh * 32;
        *(uint4*)(base)                = ((const uint4*)h0)[0];
        *(uint4*)(base + 16)           = ((const uint4*)h0)[1];
        *(uint4*)(base + A_SPLIT)      = ((const uint4*)h1)[0];
        *(uint4*)(base + A_SPLIT + 16) = ((const uint4*)h1)[1];
    };

    // ---- ldmatrix addresses (identical geometry to R7: 64B rows, 80B stride)
    const int a_mt = lane >> 3;
    const uint32_t a_addr0 = sb + (wm * 32 + (lane & 7) + ((a_mt & 1) << 3)) * A_ROW
                           + (a_mt >> 1) * 16;
    const int l15 = lane & 15;
    const uint32_t b_addr0 = sb + B_OFF + (wn * 64 + (l15 & 7)) * A_ROW
                           + (l15 >> 3) * 16;

    auto compute = [&](int b) {
        uint32_t af[2][2][2][4];   // [split][m][kk][frag]
#pragma unroll
        for (int p = 0; p < 2; p++)
#pragma unroll
            for (int m = 0; m < 2; m++)
#pragma unroll
                for (int kk = 0; kk < 2; kk++)
                    LDMATRIX_X4(af[p][m][kk],
                        a_addr0 + b * A_BUF + p * A_SPLIT + m * 16 * A_ROW + kk * 32);
#pragma unroll
        for (int nt = 0; nt < 8; nt++) {
            uint32_t bf[2][2][2];  // [split][kk][frag]
#pragma unroll
            for (int p = 0; p < 2; p++)
#pragma unroll
                for (int kk = 0; kk < 2; kk++)
                    LDMATRIX_X2(bf[p][kk],
                        b_addr0 + b * B_BUF + p * B_SPLIT + nt * 8 * A_ROW + kk * 32);
#pragma unroll
            for (int m = 0; m < 2; m++) {
                float ch[4];       // one 6-mma chain per stage (C=0 seeded)
                MMA_INIT(ch, af[0][m][0], bf[0][0]);   // x0*w0 kk0
                MMA_ACC (ch, af[0][m][0], bf[1][0]);   // x0*w1 kk0
                MMA_ACC (ch, af[1][m][0], bf[0][0]);   // x1*w0 kk0
                MMA_ACC (ch, af[0][m][1], bf[0][1]);   // x0*w0 kk1
                MMA_ACC (ch, af[0][m][1], bf[1][1]);   // x0*w1 kk1
                MMA_ACC (ch, af[1][m][1], bf[0][1]);   // x1*w0 kk1
#pragma unroll
                for (int k = 0; k < 4; k++) {          // Kahan master add (RN)
                    float y = __fadd_rn(ch[k], -cmp[m][nt][k]);
                    float t = __fadd_rn(acc[m][nt][k], y);
                    cmp[m][nt][k] = __fadd_rn(__fadd_rn(t, -acc[m][nt][k]), -y);
                    acc[m][nt][k] = t;
                }
            }
        }
    };

    // ---- prologue ----
    a_ldg(0);
    b_cpasync(0, 0);
    a_sts(0);
    asm volatile("cp.async.wait_group 0;" ::: "memory");
    __syncthreads();

    // ---- mainloop ----
    for (int s = 0; s < NST; s++) {
        const int b = s & 1;
        const bool more = (s + 1 < NST);
        if (more) {
            a_ldg(s + 1);
            b_cpasync(s + 1, b ^ 1);
        }
        compute(b);
        if (more) a_sts(b ^ 1);
        asm volatile("cp.async.wait_group 0;" ::: "memory");
        __syncthreads();
    }

    // ---- epilogue: undo 2^16 scaling (exact) ----
    const float SC = 1.0f / 65536.0f;
#pragma unroll
    for (int m = 0; m < 2; m++) {
#pragma unroll
        for (int nt = 0; nt < 8; nt++) {
            const int row = bm + wm * 32 + m * 16 + (lane >> 2);
            const int col = bn + wn * 64 + nt * 8 + ((lane & 3) << 1);
            float* cp = C + (size_t)row * NEXP + col;
            *(float2*)cp = make_float2(acc[m][nt][0] * SC, acc[m][nt][1] * SC);
            *(float2*)(cp + 8 * NEXP) = make_float2(acc[m][nt][2] * SC, acc[m][nt][3] * SC);
        }
    }
}

// ======================== routing: one warp per token =======================
__global__ __launch_bounds__(256) void routing_kernel(
    const float* __restrict__ logits, const float* __restrict__ bias,
    float* __restrict__ out_idx, float* __restrict__ out_w, int T)
{
    const int wip  = threadIdx.x >> 5;
    const int lane = threadIdx.x & 31;
    const int t = blockIdx.x * 8 + wip;
    if (t >= T) return;

    __shared__ float s_sc[8][256];
    __shared__ float s_sr[8][256];
    __shared__ float s_gv[8][8];
    __shared__ int   s_gi[8][8];

    float* sc = s_sc[wip];
    float* sr = s_sr[wip];
    const float* lrow = logits + (size_t)t * 256;

#pragma unroll
    for (int i = 0; i < 8; i++) {
        int e = i * 32 + lane;
        float l = lrow[e];
        float s = 1.0f / (1.0f + expf(-l));
        sc[e] = s;
        sr[e] = s + bias[e];
    }
    __syncwarp();

    float gscore = -INFINITY;
    if (lane < 8) {
        float m1 = -INFINITY, m2 = -INFINITY;
#pragma unroll
        for (int j = 0; j < 32; j++) {
            float v = sr[lane * 32 + ((j + lane * 4) & 31)];
            if (v > m1) { m2 = m1; m1 = v; }
            else if (v > m2) { m2 = v; }
        }
        gscore = m1 + m2;
    }

    float gs[8];
#pragma unroll
    for (int g = 0; g < 8; g++) gs[g] = __shfl_sync(0xffffffffu, gscore, g);
    unsigned gmask = 0;
#pragma unroll
    for (int k = 0; k < 4; k++) {
        int bi = -1; float bv = -INFINITY;
#pragma unroll
        for (int g = 0; g < 8; g++) {
            bool taken = (gmask >> g) & 1u;
            if (!taken && gs[g] > bv) { bv = gs[g]; bi = g; }
        }
        gmask |= 1u << bi;
    }

    float vals[8];
#pragma unroll
    for (int i = 0; i < 8; i++)
        vals[i] = ((gmask >> i) & 1u) ? sr[i * 32 + lane] : -INFINITY;

    float sum = 0.0f;
    for (int k = 0; k < 8; k++) {
        float bv = -INFINITY; int bi = 0x7fffffff;
#pragma unroll
        for (int i = 0; i < 8; i++) {
            int e = i * 32 + lane;
            if (vals[i] > bv || (vals[i] == bv && e < bi)) { bv = vals[i]; bi = e; }
        }
#pragma unroll
        for (int off = 16; off; off >>= 1) {
            float ov = __shfl_xor_sync(0xffffffffu, bv, off);
            int   oi = __shfl_xor_sync(0xffffffffu, bi, off);
            if (ov > bv || (ov == bv && oi < bi)) { bv = ov; bi = oi; }
        }
        if ((bi & 31) == lane) vals[bi >> 5] = -INFINITY;
        float g = sc[bi];
        sum += g;
        if (lane == 0) { s_gv[wip][k] = g; s_gi[wip][k] = bi; }
    }
    __syncwarp();

    if (lane < 8) {
        float w = s_gv[wip][lane] / (sum + 1e-20f) * 2.5f;
        out_w[(size_t)t * 8 + lane]   = w;
        out_idx[(size_t)t * 8 + lane] = (float)s_gi[wip][lane];
    }
}

// ============================== launch ======================================
extern "C" void kernel_launch(void* const* d_in, const int* in_sizes, int n_in,
                              void* d_out, int out_size)
{
    const float* X    = (const float*)d_in[0];  // [T, H]
    const float* W    = (const float*)d_in[1];  // [E, H]
    const float* bias = (const float*)d_in[2];  // [E]

    const int E = in_sizes[2];
    const int H = in_sizes[1] / E;
    const int T = in_sizes[0] / H;

    float* out     = (float*)d_out;
    float* out_idx = out;
    float* out_w   = out + (size_t)T * 8;

    float* logits;
    if ((size_t)out_size >= (size_t)T * 16 + (size_t)T * E) {
        logits = out + (size_t)T * 16;
    } else {
        float* p;
        cudaGetSymbolAddress((void**)&p, g_logits_scratch);
        logits = p;
    }

    // 1) W -> two fp16 split arrays (scaled by 2^12)
    wsplit_kernel<<<(E * H / 4 + 255) / 256, 256>>>(W);

    // 2) tensor-core split GEMM -> logits
    cudaFuncSetAttribute(gemm_fp16_split,
                         cudaFuncAttributeMaxDynamicSharedMemorySize, GEMM_SMEM);
    dim3 grid(E / 128, T / 128);
    gemm_fp16_split<<<grid, 256, GEMM_SMEM>>>(X, logits);

    // 3) routing
    routing_kernel<<<(T + 7) / 8, 256>>>(logits, bias, out_idx, out_w, T);
}